// round 16
// baseline (speedup 1.0000x reference)
#include <cuda_runtime.h>
#include <cuda_bf16.h>
#include <cstdint>

#define IN_F     4096
#define OUT_F    11008
#define MROWS    32
#define GRP      128
#define KSPLIT   4
#define KPER     (IN_F / KSPLIT)          // 1024
#define STAGE_K  32
#define NSTAGES  (KPER / STAGE_K)         // 32
#define WNBUF    3
#define NTILE    64
#define CTAS_COL (OUT_F / NTILE)          // 172
#define THREADS  128

#define XROW_B   272                      // xs row: 256B bf16 + 16B pad (ldmatrix conflict-free)
#define XSTILE_B (MROWS * XROW_B)         // 8704 per group tile
#define WROW_B   272                      // W row: 64 int32 (256B) + 16B pad -> conflict-free LDS
#define WSTAGE_B (STAGE_K * WROW_B)       // 8704 per stage

// pre-converted bf16 x (written by init kernel), k-contiguous per row
__device__ __nv_bfloat16 g_xbf[(size_t)MROWS * IN_F];   // 256 KB

__device__ __forceinline__ float bfr(float v) {
    return __bfloat162float(__float2bfloat16(v));
}

__device__ __forceinline__ uint32_t pack_bf16x2(float hi, float lo) {
    uint32_t r;
    asm("cvt.rn.bf16x2.f32 %0, %1, %2;" : "=r"(r) : "f"(hi), "f"(lo));
    return r;
}

__device__ __forceinline__ void hmma(float c[4], const uint32_t a[4],
                                     uint32_t b0, uint32_t b1) {
    asm volatile(
        "mma.sync.aligned.m16n8k16.row.col.f32.bf16.bf16.f32 "
        "{%0,%1,%2,%3}, {%4,%5,%6,%7}, {%8,%9}, {%0,%1,%2,%3};"
        : "+f"(c[0]), "+f"(c[1]), "+f"(c[2]), "+f"(c[3])
        : "r"(a[0]), "r"(a[1]), "r"(a[2]), "r"(a[3]), "r"(b0), "r"(b1));
}

// ---------------------------------------------------------------------------
// Init: bias-init out + pre-convert x -> bf16. Releases the dependent qmain
// launch immediately (PDL trigger); qmain's gds() still waits for full
// completion + memory flush before reading g_xbf / out.
// ---------------------------------------------------------------------------
__global__ void init_kernel(const float* __restrict__ bias,
                            const float* __restrict__ x,
                            float* __restrict__ out)
{
#if __CUDA_ARCH__ >= 900
    cudaTriggerProgrammaticLaunchCompletion();
#endif
    const int idx = blockIdx.x * blockDim.x + threadIdx.x;
    if (idx < OUT_F) {
        float b = bfr(bias[idx]);
        #pragma unroll
        for (int s = 0; s < MROWS; s++)
            out[(size_t)s * OUT_F + idx] = b;
    }
    const int stride = gridDim.x * blockDim.x;
    for (int i = idx; i < (MROWS * IN_F) / 2; i += stride) {
        float2 v = ((const float2*)x)[i];
        ((uint32_t*)g_xbf)[i] = pack_bf16x2(v.y, v.x);
    }
}

// ---------------------------------------------------------------------------
// R15 GEMM with a PDL prologue: issue 2 weight stages (independent of init),
// THEN cudaGridDependencySynchronize(), THEN the x tile. Steady state is
// byte-identical to R15: cp.async rings for weights (3 buf, 2 in flight) and
// per-group bf16-x tiles; B converts on-read ((qw-qz) 5-bit, bf16-exact);
// per-group scale in register epilogue on C columns (exact).
// ---------------------------------------------------------------------------
__global__ void __launch_bounds__(THREADS, 5)
qmain(const int* __restrict__ qweight, const int* __restrict__ qzeros,
      const float* __restrict__ scales, float* __restrict__ out)
{
    __shared__ __align__(16) uint8_t xs_raw[2 * XSTILE_B];       // 17408 B
    __shared__ __align__(16) uint8_t ws_raw[WNBUF * WSTAGE_B];   // 26112 B

    uint32_t xs_b, ws_b;
    asm("{ .reg .u64 t; cvta.to.shared.u64 t, %1; cvt.u32.u64 %0, t; }"
        : "=r"(xs_b) : "l"(xs_raw));
    asm("{ .reg .u64 t; cvta.to.shared.u64 t, %1; cvt.u32.u64 %0, t; }"
        : "=r"(ws_b) : "l"(ws_raw));

    const int tid   = threadIdx.x;
    const int w     = tid >> 5;
    const int l     = tid & 31;
    const int bx    = blockIdx.x;
    const int ctile = bx % CTAS_COL;
    const int kq    = bx / CTAS_COL;
    const int o0    = ctile * NTILE;
    const int k0    = kq * KPER;

    const int gid = l >> 2;
    const int tig = l & 3;
    const int nc0 = o0 + w * 16 + gid;      // B column, t=0
    const int nc1 = nc0 + 8;                // B column, t=1
    const int cc  = o0 + w * 16 + 2 * tig;  // C column base

    const uint32_t a_lane_off = (uint32_t)(l & 15) * XROW_B + (uint32_t)(l >> 4) * 16;
    const uint32_t b_off0 = (uint32_t)(2 * tig) * WROW_B + (uint32_t)(w * 16 + gid) * 4;
    const uint32_t b_off1 = b_off0 + 32;    // +8 cols

    // cp.async mapping: row = tid>>4 (+8j), seg = tid&15 (16B); 4 ops/thread
    const int cp_row0 = tid >> 4;
    const int cp_seg  = tid & 15;

    float ct[2][2][4], cg[2][2][4];
    #pragma unroll
    for (int mi = 0; mi < 2; mi++)
        #pragma unroll
        for (int t = 0; t < 2; t++)
            #pragma unroll
            for (int r = 0; r < 4; r++) { ct[mi][t][r] = 0.0f; cg[mi][t][r] = 0.0f; }

    int qz0 = 0, qz1 = 0;

    auto issue_w = [&](int s) {
        const uint32_t dst0 = ws_b + (uint32_t)(s % WNBUF) * WSTAGE_B;
        const int* src0 = qweight + (size_t)(k0 + s * STAGE_K) * OUT_F + o0;
        #pragma unroll
        for (int j = 0; j < 4; j++) {
            int row = cp_row0 + 8 * j;
            uint32_t dst = dst0 + (uint32_t)row * WROW_B + (uint32_t)cp_seg * 16;
            const int* src = src0 + (size_t)row * OUT_F + cp_seg * 4;
            asm volatile("cp.async.cg.shared.global [%0], [%1], 16;" :: "r"(dst), "l"(src));
        }
    };
    auto issue_x = [&](int g) {
        const uint32_t dst0 = xs_b + (uint32_t)(g & 1) * XSTILE_B;
        const __nv_bfloat16* src0 = g_xbf + (size_t)(k0 + g * GRP);
        #pragma unroll
        for (int j = 0; j < 4; j++) {
            int s = cp_row0 + 8 * j;
            uint32_t dst = dst0 + (uint32_t)s * XROW_B + (uint32_t)cp_seg * 16;
            const __nv_bfloat16* src = src0 + (size_t)s * IN_F + cp_seg * 8;
            asm volatile("cp.async.cg.shared.global [%0], [%1], 16;" :: "r"(dst), "l"(src));
        }
    };

    // ---- PDL prologue: weight prefetch overlaps the init kernel ----
    issue_w(0);
    asm volatile("cp.async.commit_group;" ::: "memory");   // G1
    issue_w(1);
    asm volatile("cp.async.commit_group;" ::: "memory");   // G2
#if __CUDA_ARCH__ >= 900
    cudaGridDependencySynchronize();   // init's g_xbf / out now visible
#endif
    issue_x(0);
    asm volatile("cp.async.commit_group;" ::: "memory");   // G3

    for (int st = 0; st < NSTAGES; st++) {
        const int g  = st >> 2;                 // 4 stages per 128k group
        const int gg = (k0 >> 7) + g;

        // wait: stage 0 needs G3 (drain all); steady state keeps 1 in flight
        if (st == 0 || st == NSTAGES - 1)
            asm volatile("cp.async.wait_group 0;" ::: "memory");
        else
            asm volatile("cp.async.wait_group 1;" ::: "memory");
        __syncthreads();   // copies visible to all; prior stage reads done (WAR)

        // issue stage st+2 (+ x tile if it starts a group)
        if (st + 2 < NSTAGES) {
            const int sn = st + 2;
            if ((sn & 3) == 0) issue_x(sn >> 2);
            issue_w(sn);
            asm volatile("cp.async.commit_group;" ::: "memory");
        }

        if ((st & 3) == 0) {
            qz0 = qzeros[(size_t)gg * OUT_F + nc0];
            qz1 = qzeros[(size_t)gg * OUT_F + nc1];
        }

        const uint32_t xbuf = xs_b + (uint32_t)(g & 1) * XSTILE_B;
        const uint32_t rbuf = ws_b + (uint32_t)(st % WNBUF) * WSTAGE_B;

        // ---- 2 k16-steps of this stage ----
        #pragma unroll
        for (int ksl = 0; ksl < 2; ksl++) {
            const int ks = 2 * (st & 3) + ksl;    // kstep within group

            uint32_t a0[4], a1[4];
            uint32_t addr0 = xbuf + a_lane_off + (uint32_t)ks * 32;
            uint32_t addr1 = addr0 + 16u * XROW_B;
            asm volatile("ldmatrix.sync.aligned.m8n8.x4.shared.b16 {%0,%1,%2,%3}, [%4];"
                         : "=r"(a0[0]), "=r"(a0[1]), "=r"(a0[2]), "=r"(a0[3]) : "r"(addr0));
            asm volatile("ldmatrix.sync.aligned.m8n8.x4.shared.b16 {%0,%1,%2,%3}, [%4];"
                         : "=r"(a1[0]), "=r"(a1[1]), "=r"(a1[2]), "=r"(a1[3]) : "r"(addr1));

            const uint32_t rb = rbuf + (uint32_t)(16 * ksl) * WROW_B;

            {   // t = 0: rows 2tig, 2tig+1, 2tig+8, 2tig+9 at local col 16w+gid
                int v0, v1, v2, v3;
                asm volatile("ld.shared.b32 %0, [%1];" : "=r"(v0) : "r"(rb + b_off0));
                asm volatile("ld.shared.b32 %0, [%1];" : "=r"(v1) : "r"(rb + b_off0 + WROW_B));
                asm volatile("ld.shared.b32 %0, [%1];" : "=r"(v2) : "r"(rb + b_off0 + 8 * WROW_B));
                asm volatile("ld.shared.b32 %0, [%1];" : "=r"(v3) : "r"(rb + b_off0 + 9 * WROW_B));
                uint32_t b0 = pack_bf16x2((float)(v1 - qz0), (float)(v0 - qz0));
                uint32_t b1 = pack_bf16x2((float)(v3 - qz0), (float)(v2 - qz0));
                hmma(cg[0][0], a0, b0, b1);
                hmma(cg[1][0], a1, b0, b1);
            }
            {   // t = 1
                int v0, v1, v2, v3;
                asm volatile("ld.shared.b32 %0, [%1];" : "=r"(v0) : "r"(rb + b_off1));
                asm volatile("ld.shared.b32 %0, [%1];" : "=r"(v1) : "r"(rb + b_off1 + WROW_B));
                asm volatile("ld.shared.b32 %0, [%1];" : "=r"(v2) : "r"(rb + b_off1 + 8 * WROW_B));
                asm volatile("ld.shared.b32 %0, [%1];" : "=r"(v3) : "r"(rb + b_off1 + 9 * WROW_B));
                uint32_t b0 = pack_bf16x2((float)(v1 - qz1), (float)(v0 - qz1));
                uint32_t b1 = pack_bf16x2((float)(v3 - qz1), (float)(v2 - qz1));
                hmma(cg[0][1], a0, b0, b1);
                hmma(cg[1][1], a1, b0, b1);
            }
        }

        // ---- group done -> scale epilogue on C columns ----
        if ((st & 3) == 3) {
            const float sA = bfr(scales[(size_t)gg * OUT_F + cc]);
            const float sB = bfr(scales[(size_t)gg * OUT_F + cc + 1]);
            const float sC = bfr(scales[(size_t)gg * OUT_F + cc + 8]);
            const float sD = bfr(scales[(size_t)gg * OUT_F + cc + 9]);
            #pragma unroll
            for (int mi = 0; mi < 2; mi++) {
                ct[mi][0][0] = fmaf(cg[mi][0][0], sA, ct[mi][0][0]);
                ct[mi][0][1] = fmaf(cg[mi][0][1], sB, ct[mi][0][1]);
                ct[mi][0][2] = fmaf(cg[mi][0][2], sA, ct[mi][0][2]);
                ct[mi][0][3] = fmaf(cg[mi][0][3], sB, ct[mi][0][3]);
                ct[mi][1][0] = fmaf(cg[mi][1][0], sC, ct[mi][1][0]);
                ct[mi][1][1] = fmaf(cg[mi][1][1], sD, ct[mi][1][1]);
                ct[mi][1][2] = fmaf(cg[mi][1][2], sC, ct[mi][1][2]);
                ct[mi][1][3] = fmaf(cg[mi][1][3], sD, ct[mi][1][3]);
                #pragma unroll
                for (int t = 0; t < 2; t++)
                    #pragma unroll
                    for (int r = 0; r < 4; r++) cg[mi][t][r] = 0.0f;
            }
        }
    }

    // ---- K-split reduction into bias-initialized output ----
    #pragma unroll
    for (int mi = 0; mi < 2; mi++) {
        int s0 = mi * 16 + gid;
        #pragma unroll
        for (int t = 0; t < 2; t++) {
            int oc = cc + t * 8;
            atomicAdd(&out[(size_t)s0 * OUT_F + oc],           ct[mi][t][0]);
            atomicAdd(&out[(size_t)s0 * OUT_F + oc + 1],       ct[mi][t][1]);
            atomicAdd(&out[(size_t)(s0 + 8) * OUT_F + oc],     ct[mi][t][2]);
            atomicAdd(&out[(size_t)(s0 + 8) * OUT_F + oc + 1], ct[mi][t][3]);
        }
    }
}

// ---------------------------------------------------------------------------
// inputs: x f32[1,32,4096], qweight i32[4096,11008], qzeros i32[32,11008],
//         scales f32[32,11008], bias f32[11008]; output f32[1,32,11008]
// ---------------------------------------------------------------------------
extern "C" void kernel_launch(void* const* d_in, const int* in_sizes, int n_in,
                              void* d_out, int out_size)
{
    const float* x       = (const float*)d_in[0];
    const int*   qweight = (const int*)  d_in[1];
    const int*   qzeros  = (const int*)  d_in[2];
    const float* scales  = (const float*)d_in[3];
    const float* bias    = (const float*)d_in[4];
    float*       out     = (float*)d_out;

    init_kernel<<<172, 256>>>(bias, x, out);

    // qmain with programmatic dependent launch (overlaps init); fallback to a
    // plain launch if the attribute is rejected (gds() degrades to no-op).
    cudaLaunchConfig_t cfg = {};
    cfg.gridDim  = dim3(CTAS_COL * KSPLIT, 1, 1);
    cfg.blockDim = dim3(THREADS, 1, 1);
    cfg.dynamicSmemBytes = 0;
    cfg.stream = 0;
    cudaLaunchAttribute attr[1];
    attr[0].id = cudaLaunchAttributeProgrammaticStreamSerialization;
    attr[0].val.programmaticStreamSerializationAllowed = 1;
    cfg.attrs = attr;
    cfg.numAttrs = 1;

    cudaError_t err = cudaLaunchKernelEx(&cfg, qmain, qweight, qzeros, scales, out);
    if (err != cudaSuccess) {
        qmain<<<CTAS_COL * KSPLIT, THREADS>>>(qweight, qzeros, scales, out);
    }
}